// round 5
// baseline (speedup 1.0000x reference)
#include <cuda_runtime.h>
#include <cstdint>
#include <cstddef>

#define T_STEPS 2048
#define BATCH   64
#define DIM     256
#define HID     256
#define NLAYER  2
#define GDIM    1024                    // 4*H
#define MROWS   (T_STEPS * BATCH)       // 131072

// ---------------- scratch (static device memory; no allocation APIs) -------
__device__ float    g_pre[(size_t)NLAYER * MROWS * GDIM];   // 1 GiB: pre-activations x@Wx + b
__device__ float    g_h[NLAYER][2][BATCH * HID];            // double-buffered hidden state
__device__ unsigned g_cnt[NLAYER];                          // per-layer arrival counters

// ---------------- packed fp32x2 helpers ------------------------------------
__device__ __forceinline__ unsigned long long pack2(float x, float y) {
    unsigned long long r;
    asm("mov.b64 %0, {%1, %2};" : "=l"(r) : "f"(x), "f"(y));
    return r;
}
__device__ __forceinline__ void unpack2(unsigned long long v, float& x, float& y) {
    asm("mov.b64 {%0, %1}, %2;" : "=f"(x), "=f"(y) : "l"(v));
}
__device__ __forceinline__ void fma2(unsigned long long& d, unsigned long long a,
                                     unsigned long long b) {
    asm("fma.rn.f32x2 %0, %1, %2, %0;" : "+l"(d) : "l"(a), "l"(b));
}

__device__ __forceinline__ float sigmoidf_(float x) {
    return 1.0f / (1.0f + expf(-x));
}

// ---------------- kernel 0: reset barrier counters each replay -------------
__global__ void k_reset() {
    if (threadIdx.x < NLAYER) g_cnt[threadIdx.x] = 0u;
}

// ---------------- kernel 1: pre[l,t,b,:] = x[t,b,:] @ Wx[l] + b[l] ---------
// GEMM per layer: M=131072 (t*64+b), K=256, N=1024. Tile 128x128, BK=32.
__global__ __launch_bounds__(256, 2) void k_pre(const float* __restrict__ x,
                                                const float* __restrict__ W,
                                                const float* __restrict__ bias) {
    __shared__ float As[32 * 132];   // [k][m], padded
    __shared__ float Bs[32 * 128];   // [k][n]

    int bid  = blockIdx.x;
    int l    = bid >> 13;            // / 8192
    int rem  = bid & 8191;
    int mt   = rem >> 3;
    int nt   = rem & 7;
    int row0 = mt << 7;
    int col0 = nt << 7;
    int tid  = threadIdx.x;
    int tm   = tid >> 4;             // 0..15
    int tn   = tid & 15;             // 0..15

    const float* Wl = W + (size_t)l * 512 * 1024;   // rows [0,256) = Wx

    unsigned long long acc[8][4];
#pragma unroll
    for (int i = 0; i < 8; i++)
#pragma unroll
        for (int j = 0; j < 4; j++) acc[i][j] = 0ULL;

    for (int kc = 0; kc < 256; kc += 32) {
        // A tile -> transposed smem
#pragma unroll
        for (int i = 0; i < 4; i++) {
            int aidx = tid + i * 256;
            int m    = aidx >> 3;
            int k4   = (aidx & 7) << 2;
            float4 v = *(const float4*)&x[(size_t)(row0 + m) * 256 + kc + k4];
            As[(k4 + 0) * 132 + m] = v.x;
            As[(k4 + 1) * 132 + m] = v.y;
            As[(k4 + 2) * 132 + m] = v.z;
            As[(k4 + 3) * 132 + m] = v.w;
        }
        // B tile (natural layout)
#pragma unroll
        for (int i = 0; i < 4; i++) {
            int kk = (tid >> 5) + i * 8;
            int n4 = (tid & 31) << 2;
            *(float4*)&Bs[kk * 128 + n4] =
                *(const float4*)&Wl[(size_t)(kc + kk) * 1024 + col0 + n4];
        }
        __syncthreads();

#pragma unroll
        for (int k = 0; k < 32; k++) {
            float4 a0 = *(const float4*)&As[k * 132 + tm * 8];
            float4 a1 = *(const float4*)&As[k * 132 + tm * 8 + 4];
            float4 b0 = *(const float4*)&Bs[k * 128 + tn * 8];
            float4 b1 = *(const float4*)&Bs[k * 128 + tn * 8 + 4];
            unsigned long long bb0 = pack2(b0.x, b0.y);
            unsigned long long bb1 = pack2(b0.z, b0.w);
            unsigned long long bb2 = pack2(b1.x, b1.y);
            unsigned long long bb3 = pack2(b1.z, b1.w);
            float av[8] = {a0.x, a0.y, a0.z, a0.w, a1.x, a1.y, a1.z, a1.w};
#pragma unroll
            for (int i = 0; i < 8; i++) {
                unsigned long long a2 = pack2(av[i], av[i]);
                fma2(acc[i][0], a2, bb0);
                fma2(acc[i][1], a2, bb1);
                fma2(acc[i][2], a2, bb2);
                fma2(acc[i][3], a2, bb3);
            }
        }
        __syncthreads();
    }

    // epilogue: add bias, store
    float bv[8];
#pragma unroll
    for (int j = 0; j < 8; j++) bv[j] = bias[l * 1024 + col0 + tn * 8 + j];
#pragma unroll
    for (int i = 0; i < 8; i++) {
        float o[8];
#pragma unroll
        for (int j = 0; j < 4; j++) unpack2(acc[i][j], o[2 * j], o[2 * j + 1]);
#pragma unroll
        for (int j = 0; j < 8; j++) o[j] += bv[j];
        size_t base = ((size_t)l * MROWS + row0 + tm * 8 + i) * 1024 + col0 + tn * 8;
        *(float4*)&g_pre[base]     = make_float4(o[0], o[1], o[2], o[3]);
        *(float4*)&g_pre[base + 4] = make_float4(o[4], o[5], o[6], o[7]);
    }
}

// ---------------- kernel 2: persistent recurrence ---------------------------
// 128 CTAs = 2 layers x 64 column-groups (4 h-cols each). 256 threads:
// b = tid>>2 (batch row), cq = tid&3 (h-col within group).
// Per step: gates[b, hcol + g*256] = pre + sum_k h[b,k] * Wh[k, ...]
__global__ __launch_bounds__(256, 1) void k_rec(const float* __restrict__ h0,
                                                const float* __restrict__ c0,
                                                const float* __restrict__ W,
                                                float* __restrict__ out) {
    extern __shared__ float smem[];
    float* Whs = smem;                 // 4096 floats: [k][cq][gate] interleaved
    float* h_s = smem + 4096;          // 64 x 260 (padded)

    int l     = blockIdx.x >> 6;
    int cg    = blockIdx.x & 63;
    int c0col = cg << 2;
    int tid   = threadIdx.x;
    int b     = tid >> 2;
    int cq    = tid & 3;
    int hcol  = c0col + cq;

    // Wh slice (rows [256,512) of W[l]) -> smem, gate-interleaved per k
    const float* Whl = W + (size_t)l * 512 * 1024 + (size_t)256 * 1024;
    for (int i = tid; i < 4096; i += 256) {
        int k = i >> 4;
        int r = i & 15;
        int q = r >> 2;
        int g = r & 3;
        Whs[i] = Whl[(size_t)k * 1024 + g * 256 + c0col + q];
    }

    // stage initial h0 (64 rows x 64 float4 per row), load private c
    const float* hsrc0 = h0 + l * BATCH * HID;
    for (int i = tid; i < 4096; i += 256) {
        int bb = i >> 6;                 // 64 float4 per row
        int k4 = (i & 63) << 2;
        *(float4*)&h_s[bb * 260 + k4] = *(const float4*)&hsrc0[bb * 256 + k4];
    }
    float c = c0[l * BATCH * HID + b * 256 + hcol];
    __syncthreads();

    const float* wbase = Whs + cq * 4;
    const float* hrow  = h_s + b * 260;
    float h_cur = 0.0f;

    for (int t = 0; t < T_STEPS; t++) {
        // prefetch pre-activations for this step (independent of barrier)
        size_t prow = ((size_t)l * MROWS + (size_t)t * BATCH + b) * 1024 + hcol;
        float pf = __ldcs(&g_pre[prow]);
        float pi = __ldcs(&g_pre[prow + 256]);
        float pg = __ldcs(&g_pre[prow + 512]);
        float po = __ldcs(&g_pre[prow + 768]);

        // recurrent dot products: fi = (f,i) pair, go = (g,o) pair
        unsigned long long fi = 0ULL, go = 0ULL;
#pragma unroll 8
        for (int k4 = 0; k4 < 256; k4 += 4) {
            float4 hv = *(const float4*)&hrow[k4];
            float hh[4] = {hv.x, hv.y, hv.z, hv.w};
#pragma unroll
            for (int j = 0; j < 4; j++) {
                float4 w = *(const float4*)&wbase[(k4 + j) * 16];
                unsigned long long a2 = pack2(hh[j], hh[j]);
                fma2(fi, a2, pack2(w.x, w.y));
                fma2(go, a2, pack2(w.z, w.w));
            }
        }
        float af, ai, ag, ao;
        unpack2(fi, af, ai);
        unpack2(go, ag, ao);
        float gf  = sigmoidf_(af + pf);
        float gi  = sigmoidf_(ai + pi);
        float gg  = tanhf(ag + pg);
        float go_ = sigmoidf_(ao + po);
        c     = gf * c + gi * gg;
        h_cur = go_ * tanhf(c);

        int wb = 1 - (t & 1);
        g_h[l][wb][b * 256 + hcol] = h_cur;
        if (l == 1) out[(size_t)t * BATCH * HID + b * 256 + hcol] = h_cur;

        if (t == T_STEPS - 1) break;

        __threadfence();
        __syncthreads();
        if (tid == 0) {
            // arrive (release), then wait for all 64 CTAs of this layer
            asm volatile("red.release.gpu.global.add.u32 [%0], %1;"
                         :: "l"(&g_cnt[l]), "r"(1u) : "memory");
            unsigned target = 64u * (unsigned)(t + 1);
            unsigned v;
            do {
                asm volatile("ld.acquire.gpu.global.u32 %0, [%1];"
                             : "=r"(v) : "l"(&g_cnt[l]) : "memory");
                if (v >= target) break;
                __nanosleep(64);
            } while (1);
        }
        __syncthreads();

        // stage h_t for next step (L2 loads — L1 is stale across CTAs)
        const float* hsrc = g_h[l][wb];
        for (int i = tid; i < 4096; i += 256) {
            int bb = i >> 6;             // 64 float4 per row
            int k4 = (i & 63) << 2;
            float4 v = __ldcg((const float4*)&hsrc[bb * 256 + k4]);
            *(float4*)&h_s[bb * 260 + k4] = v;
        }
        __syncthreads();
    }

    // final hidden / cell states
    size_t OUTH = (size_t)T_STEPS * BATCH * HID;
    out[OUTH + (size_t)l * BATCH * HID + b * 256 + hcol]                       = h_cur;
    out[OUTH + (size_t)NLAYER * BATCH * HID + (size_t)l * BATCH * HID
        + b * 256 + hcol]                                                       = c;
}

// ---------------- launch ----------------------------------------------------
extern "C" void kernel_launch(void* const* d_in, const int* in_sizes, int n_in,
                              void* d_out, int out_size) {
    const float* x    = (const float*)d_in[0];
    const float* h0   = (const float*)d_in[1];
    const float* c0   = (const float*)d_in[2];
    const float* W    = (const float*)d_in[3];
    const float* bias = (const float*)d_in[4];
    float* out = (float*)d_out;

    size_t dsmem = (size_t)(4096 + 64 * 260) * sizeof(float);   // 82,944 B
    cudaFuncSetAttribute(k_rec, cudaFuncAttributeMaxDynamicSharedMemorySize,
                         (int)dsmem);

    k_reset<<<1, 32>>>();
    k_pre<<<NLAYER * (MROWS / 128) * (GDIM / 128), 256>>>(x, W, bias);
    k_rec<<<NLAYER * 64, 256, dsmem>>>(h0, c0, W, out);
}

// round 6
// speedup vs baseline: 1.0408x; 1.0408x over previous
#include <cuda_runtime.h>
#include <cstdint>
#include <cstddef>

#define T_STEPS 2048
#define BATCH   64
#define DIM     256
#define HID     256
#define NLAYER  2
#define GDIM    1024                    // 4*H
#define MROWS   (T_STEPS * BATCH)       // 131072

// ---------------- scratch (static device memory; no allocation APIs) -------
__device__ float    g_pre[(size_t)NLAYER * MROWS * GDIM];   // 1 GiB: pre-activations x@Wx + b
__device__ float    g_h[NLAYER][2][BATCH * HID];            // double-buffered hidden state
__device__ unsigned g_cnt[NLAYER];                          // per-layer arrival counters

// ---------------- packed fp32x2 helpers ------------------------------------
__device__ __forceinline__ unsigned long long pack2(float x, float y) {
    unsigned long long r;
    asm("mov.b64 %0, {%1, %2};" : "=l"(r) : "f"(x), "f"(y));
    return r;
}
__device__ __forceinline__ void unpack2(unsigned long long v, float& x, float& y) {
    asm("mov.b64 {%0, %1}, %2;" : "=f"(x), "=f"(y) : "l"(v));
}
__device__ __forceinline__ void fma2(unsigned long long& d, unsigned long long a,
                                     unsigned long long b) {
    asm("fma.rn.f32x2 %0, %1, %2, %0;" : "+l"(d) : "l"(a), "l"(b));
}

__device__ __forceinline__ float sigmoidf_(float x) {
    return 1.0f / (1.0f + expf(-x));
}

// ---------------- kernel 1: pre[l,t,b,:] = x[t,b,:] @ Wx[l] + b[l] ---------
// GEMM per layer: M=131072 (t*64+b), K=256, N=1024. Tile 128x128, BK=32.
// Block 0 also resets the k_rec barrier counters (runs before k_rec in-stream).
__global__ __launch_bounds__(256, 2) void k_pre(const float* __restrict__ x,
                                                const float* __restrict__ W,
                                                const float* __restrict__ bias) {
    __shared__ __align__(16) float As[32 * 132];   // [k][m], padded
    __shared__ __align__(16) float Bs[32 * 128];   // [k][n]

    if (blockIdx.x == 0 && threadIdx.x < NLAYER) g_cnt[threadIdx.x] = 0u;

    int bid  = blockIdx.x;
    int l    = bid >> 13;            // / 8192
    int rem  = bid & 8191;
    int mt   = rem >> 3;
    int nt   = rem & 7;
    int row0 = mt << 7;
    int col0 = nt << 7;
    int tid  = threadIdx.x;
    int tm   = tid >> 4;             // 0..15
    int tn   = tid & 15;             // 0..15

    const float* Wl = W + (size_t)l * 512 * 1024;   // rows [0,256) = Wx

    unsigned long long acc[8][4];
#pragma unroll
    for (int i = 0; i < 8; i++)
#pragma unroll
        for (int j = 0; j < 4; j++) acc[i][j] = 0ULL;

    for (int kc = 0; kc < 256; kc += 32) {
        // A tile -> transposed smem
#pragma unroll
        for (int i = 0; i < 4; i++) {
            int aidx = tid + i * 256;
            int m    = aidx >> 3;
            int k4   = (aidx & 7) << 2;
            float4 v = *(const float4*)&x[(size_t)(row0 + m) * 256 + kc + k4];
            As[(k4 + 0) * 132 + m] = v.x;
            As[(k4 + 1) * 132 + m] = v.y;
            As[(k4 + 2) * 132 + m] = v.z;
            As[(k4 + 3) * 132 + m] = v.w;
        }
        // B tile (natural layout)
#pragma unroll
        for (int i = 0; i < 4; i++) {
            int kk = (tid >> 5) + i * 8;
            int n4 = (tid & 31) << 2;
            *(float4*)&Bs[kk * 128 + n4] =
                *(const float4*)&Wl[(size_t)(kc + kk) * 1024 + col0 + n4];
        }
        __syncthreads();

#pragma unroll
        for (int k = 0; k < 32; k++) {
            float4 a0 = *(const float4*)&As[k * 132 + tm * 8];
            float4 a1 = *(const float4*)&As[k * 132 + tm * 8 + 4];
            // B pairs straight from LDS.128 (no pack MOVs)
            ulonglong2 bb01 = *(const ulonglong2*)&Bs[k * 128 + tn * 8];
            ulonglong2 bb23 = *(const ulonglong2*)&Bs[k * 128 + tn * 8 + 4];
            float av[8] = {a0.x, a0.y, a0.z, a0.w, a1.x, a1.y, a1.z, a1.w};
#pragma unroll
            for (int i = 0; i < 8; i++) {
                unsigned long long a2 = pack2(av[i], av[i]);
                fma2(acc[i][0], a2, bb01.x);
                fma2(acc[i][1], a2, bb01.y);
                fma2(acc[i][2], a2, bb23.x);
                fma2(acc[i][3], a2, bb23.y);
            }
        }
        __syncthreads();
    }

    // epilogue: add bias, store
    float bv[8];
#pragma unroll
    for (int j = 0; j < 8; j++) bv[j] = bias[l * 1024 + col0 + tn * 8 + j];
#pragma unroll
    for (int i = 0; i < 8; i++) {
        float o[8];
#pragma unroll
        for (int j = 0; j < 4; j++) unpack2(acc[i][j], o[2 * j], o[2 * j + 1]);
#pragma unroll
        for (int j = 0; j < 8; j++) o[j] += bv[j];
        size_t base = ((size_t)l * MROWS + row0 + tm * 8 + i) * 1024 + col0 + tn * 8;
        *(float4*)&g_pre[base]     = make_float4(o[0], o[1], o[2], o[3]);
        *(float4*)&g_pre[base + 4] = make_float4(o[4], o[5], o[6], o[7]);
    }
}

// ---------------- kernel 2: persistent recurrence ---------------------------
// 128 CTAs = 2 layers x 64 column-groups (4 h-cols each). 256 threads:
// b = tid>>2 (batch row), cq = tid&3 (h-col within group).
__global__ __launch_bounds__(256, 1) void k_rec(const float* __restrict__ h0,
                                                const float* __restrict__ c0,
                                                const float* __restrict__ W,
                                                float* __restrict__ out) {
    extern __shared__ float smem[];
    float* Whs = smem;                 // 4096 floats: [k][cq][gate] interleaved
    float* h_s = smem + 4096;          // 64 x 260 (padded)

    int l     = blockIdx.x >> 6;
    int cg    = blockIdx.x & 63;
    int c0col = cg << 2;
    int tid   = threadIdx.x;
    int b     = tid >> 2;
    int cq    = tid & 3;
    int hcol  = c0col + cq;

    // Wh slice (rows [256,512) of W[l]) -> smem, gate-interleaved per k
    const float* Whl = W + (size_t)l * 512 * 1024 + (size_t)256 * 1024;
    for (int i = tid; i < 4096; i += 256) {
        int k = i >> 4;
        int r = i & 15;
        int q = r >> 2;
        int g = r & 3;
        Whs[i] = Whl[(size_t)k * 1024 + g * 256 + c0col + q];
    }

    // stage initial h0 (64 rows x 64 float4 per row), load private c
    const float* hsrc0 = h0 + l * BATCH * HID;
    for (int i = tid; i < 4096; i += 256) {
        int bb = i >> 6;
        int k4 = (i & 63) << 2;
        *(float4*)&h_s[bb * 260 + k4] = *(const float4*)&hsrc0[bb * 256 + k4];
    }
    float c = c0[l * BATCH * HID + b * 256 + hcol];
    __syncthreads();

    const float* wbase = Whs + cq * 4;
    const float* hrow  = h_s + b * 260;
    float h_cur = 0.0f;

    for (int t = 0; t < T_STEPS; t++) {
        // pre-activations for this step (streaming; independent of barrier)
        size_t prow = ((size_t)l * MROWS + (size_t)t * BATCH + b) * 1024 + hcol;
        float pf = __ldcs(&g_pre[prow]);
        float pi = __ldcs(&g_pre[prow + 256]);
        float pg = __ldcs(&g_pre[prow + 512]);
        float po = __ldcs(&g_pre[prow + 768]);

        // recurrent dot products, 4 independent chains (fi/go x even/odd)
        unsigned long long fiA = 0ULL, goA = 0ULL, fiB = 0ULL, goB = 0ULL;
#pragma unroll 8
        for (int k4 = 0; k4 < 256; k4 += 8) {
            float4 hv0 = *(const float4*)&hrow[k4];
            float4 hv1 = *(const float4*)&hrow[k4 + 4];
            float hh[8] = {hv0.x, hv0.y, hv0.z, hv0.w, hv1.x, hv1.y, hv1.z, hv1.w};
#pragma unroll
            for (int j = 0; j < 8; j++) {
                ulonglong2 wv = *(const ulonglong2*)&wbase[(k4 + j) * 16];
                unsigned long long a2 = pack2(hh[j], hh[j]);
                if (j & 1) { fma2(fiB, a2, wv.x); fma2(goB, a2, wv.y); }
                else       { fma2(fiA, a2, wv.x); fma2(goA, a2, wv.y); }
            }
        }
        float af0, ai0, ag0, ao0, af1, ai1, ag1, ao1;
        unpack2(fiA, af0, ai0);
        unpack2(fiB, af1, ai1);
        unpack2(goA, ag0, ao0);
        unpack2(goB, ag1, ao1);
        float gf  = sigmoidf_(af0 + af1 + pf);
        float gi  = sigmoidf_(ai0 + ai1 + pi);
        float gg  = tanhf(ag0 + ag1 + pg);
        float go_ = sigmoidf_(ao0 + ao1 + po);
        c     = gf * c + gi * gg;
        h_cur = go_ * tanhf(c);

        int wb = 1 - (t & 1);
        g_h[l][wb][b * 256 + hcol] = h_cur;
        if (l == 1) out[(size_t)t * BATCH * HID + b * 256 + hcol] = h_cur;

        if (t == T_STEPS - 1) break;

        __syncthreads();                // all stores of this CTA issued
        if (tid == 0) {
            // release-arrive orders all prior CTA writes (hb via bar.sync)
            asm volatile("red.release.gpu.global.add.u32 [%0], %1;"
                         :: "l"(&g_cnt[l]), "r"(1u) : "memory");
            unsigned target = 64u * (unsigned)(t + 1);
            unsigned v;
            do {
                asm volatile("ld.acquire.gpu.global.u32 %0, [%1];"
                             : "=r"(v) : "l"(&g_cnt[l]) : "memory");
            } while (v < target);
        }
        __syncthreads();

        // stage h_t for next step (L2 loads — L1 is stale across CTAs)
        const float* hsrc = g_h[l][wb];
#pragma unroll 4
        for (int i = tid; i < 4096; i += 256) {
            int bb = i >> 6;
            int k4 = (i & 63) << 2;
            float4 v = __ldcg((const float4*)&hsrc[bb * 256 + k4]);
            *(float4*)&h_s[bb * 260 + k4] = v;
        }
        __syncthreads();
    }

    // final hidden / cell states
    size_t OUTH = (size_t)T_STEPS * BATCH * HID;
    out[OUTH + (size_t)l * BATCH * HID + b * 256 + hcol]                       = h_cur;
    out[OUTH + (size_t)NLAYER * BATCH * HID + (size_t)l * BATCH * HID
        + b * 256 + hcol]                                                       = c;
}

// ---------------- launch ----------------------------------------------------
extern "C" void kernel_launch(void* const* d_in, const int* in_sizes, int n_in,
                              void* d_out, int out_size) {
    const float* x    = (const float*)d_in[0];
    const float* h0   = (const float*)d_in[1];
    const float* c0   = (const float*)d_in[2];
    const float* W    = (const float*)d_in[3];
    const float* bias = (const float*)d_in[4];
    float* out = (float*)d_out;

    size_t dsmem = (size_t)(4096 + 64 * 260) * sizeof(float);   // 82,944 B
    cudaFuncSetAttribute(k_rec, cudaFuncAttributeMaxDynamicSharedMemorySize,
                         (int)dsmem);

    k_pre<<<NLAYER * (MROWS / 128) * (GDIM / 128), 256>>>(x, W, bias);
    k_rec<<<NLAYER * 64, 256, dsmem>>>(h0, c0, W, out);
}